// round 1
// baseline (speedup 1.0000x reference)
#include <cuda_runtime.h>
#include <cstdint>

// Haar IDWT2: out[2i,2j]=(LL+LH+HL+HH)/2, out[2i,2j+1]=(LL+LH-HL-HH)/2,
//             out[2i+1,2j]=(LL-LH+HL-HH)/2, out[2i+1,2j+1]=(LL-LH-HL+HH)/2
// Shapes: inputs [B,C,H2,W2] = [16,64,128,128] fp32; output [B,C,256,256] fp32.

static constexpr int Bdim = 16;
static constexpr int Cdim = 64;
static constexpr int H2   = 128;
static constexpr int W2   = 128;
static constexpr int W2V  = W2 / 4;              // float4 groups per input row = 32
static constexpr long long NCOEF = (long long)Bdim * Cdim * H2 * W2;   // 16,777,216
static constexpr int NTHREADS_TOTAL = (int)(NCOEF / 4);                // 4,194,304

__global__ __launch_bounds__(256)
void idwt_haar_kernel(const float* __restrict__ LL,
                      const float* __restrict__ LH,
                      const float* __restrict__ HL,
                      const float* __restrict__ HH,
                      float* __restrict__ out)
{
    int tid = blockIdx.x * blockDim.x + threadIdx.x;
    // tid -> (row, col4): row = bc*H2 + i over all images, col4 in [0, 32)
    int col4 = tid & (W2V - 1);          // W2V = 32, power of 2
    int row  = tid >> 5;                 // tid / 32

    // 128-bit loads of 4 consecutive coefficients
    const float4* LL4 = reinterpret_cast<const float4*>(LL);
    const float4* LH4 = reinterpret_cast<const float4*>(LH);
    const float4* HL4 = reinterpret_cast<const float4*>(HL);
    const float4* HH4 = reinterpret_cast<const float4*>(HH);

    long long in_off = (long long)row * W2V + col4;
    float4 ll = __ldg(&LL4[in_off]);
    float4 lh = __ldg(&LH4[in_off]);
    float4 hl = __ldg(&HL4[in_off]);
    float4 hh = __ldg(&HH4[in_off]);

    // per-lane butterflies (×0.5)
    float a0 = (ll.x + lh.x + hl.x + hh.x) * 0.5f;
    float b0 = (ll.x + lh.x - hl.x - hh.x) * 0.5f;
    float c0 = (ll.x - lh.x + hl.x - hh.x) * 0.5f;
    float d0 = (ll.x - lh.x - hl.x + hh.x) * 0.5f;

    float a1 = (ll.y + lh.y + hl.y + hh.y) * 0.5f;
    float b1 = (ll.y + lh.y - hl.y - hh.y) * 0.5f;
    float c1 = (ll.y - lh.y + hl.y - hh.y) * 0.5f;
    float d1 = (ll.y - lh.y - hl.y + hh.y) * 0.5f;

    float a2 = (ll.z + lh.z + hl.z + hh.z) * 0.5f;
    float b2 = (ll.z + lh.z - hl.z - hh.z) * 0.5f;
    float c2 = (ll.z - lh.z + hl.z - hh.z) * 0.5f;
    float d2 = (ll.z - lh.z - hl.z + hh.z) * 0.5f;

    float a3 = (ll.w + lh.w + hl.w + hh.w) * 0.5f;
    float b3 = (ll.w + lh.w - hl.w - hh.w) * 0.5f;
    float c3 = (ll.w - lh.w + hl.w - hh.w) * 0.5f;
    float d3 = (ll.w - lh.w - hl.w + hh.w) * 0.5f;

    // output addressing: image bc, coefficient row i -> output rows 2i, 2i+1
    int bc = row >> 7;                   // row / H2 (H2 = 128)
    int i  = row & (H2 - 1);
    const int OW = 2 * W2;               // 256
    long long obase = ((long long)bc * (2 * H2) + 2 * i) * OW + (long long)col4 * 8;

    float4* out4_r0 = reinterpret_cast<float4*>(out + obase);
    float4* out4_r1 = reinterpret_cast<float4*>(out + obase + OW);

    out4_r0[0] = make_float4(a0, b0, a1, b1);
    out4_r0[1] = make_float4(a2, b2, a3, b3);
    out4_r1[0] = make_float4(c0, d0, c1, d1);
    out4_r1[1] = make_float4(c2, d2, c3, d3);
}

extern "C" void kernel_launch(void* const* d_in, const int* in_sizes, int n_in,
                              void* d_out, int out_size)
{
    const float* LL = (const float*)d_in[0];
    const float* LH = (const float*)d_in[1];
    const float* HL = (const float*)d_in[2];
    const float* HH = (const float*)d_in[3];
    float* out = (float*)d_out;

    const int threads = 256;
    const int blocks = NTHREADS_TOTAL / threads;   // 16384
    idwt_haar_kernel<<<blocks, threads>>>(LL, LH, HL, HH, out);
}

// round 4
// speedup vs baseline: 1.4490x; 1.4490x over previous
#include <cuda_runtime.h>
#include <cstdint>

// Haar IDWT2: out[2i,2j]=(LL+LH+HL+HH)/2, out[2i,2j+1]=(LL+LH-HL-HH)/2,
//             out[2i+1,2j]=(LL-LH+HL-HH)/2, out[2i+1,2j+1]=(LL-LH-HL+HH)/2
// Shapes: inputs [B,C,H2,W2] = [16,64,128,128] fp32; output [B,C,256,256] fp32.
//
// R1: 2 coefficients per thread. Loads: float2 per subband (warp: 256B
// contiguous). Stores: one float4 per output row per thread at col2*4 floats
// -> warp store = 512B contiguous = minimal L1 wavefronts (was 2x inflated).

static constexpr int Bdim = 16;
static constexpr int Cdim = 64;
static constexpr int H2   = 128;
static constexpr int W2   = 128;
static constexpr int W2V2 = W2 / 2;              // float2 groups per input row = 64
static constexpr long long NCOEF = (long long)Bdim * Cdim * H2 * W2;   // 16,777,216
static constexpr int NTHREADS_TOTAL = (int)(NCOEF / 2);                // 8,388,608

__global__ __launch_bounds__(256)
void idwt_haar_kernel(const float2* __restrict__ LL2,
                      const float2* __restrict__ LH2,
                      const float2* __restrict__ HL2,
                      const float2* __restrict__ HH2,
                      float* __restrict__ out)
{
    int tid = blockIdx.x * blockDim.x + threadIdx.x;
    int col2 = tid & (W2V2 - 1);         // 0..63
    int row  = tid >> 6;                 // global coefficient row index

    long long in_off = (long long)row * W2V2 + col2;
    float2 ll = __ldg(&LL2[in_off]);
    float2 lh = __ldg(&LH2[in_off]);
    float2 hl = __ldg(&HL2[in_off]);
    float2 hh = __ldg(&HH2[in_off]);

    // butterflies (x0.5)
    float s0 = ll.x + lh.x, t0 = ll.x - lh.x;
    float u0 = hl.x + hh.x, v0 = hl.x - hh.x;
    float a0 = (s0 + u0) * 0.5f;
    float b0 = (s0 - u0) * 0.5f;
    float c0 = (t0 + v0) * 0.5f;
    float d0 = (t0 - v0) * 0.5f;

    float s1 = ll.y + lh.y, t1 = ll.y - lh.y;
    float u1 = hl.y + hh.y, v1 = hl.y - hh.y;
    float a1 = (s1 + u1) * 0.5f;
    float b1 = (s1 - u1) * 0.5f;
    float c1 = (t1 + v1) * 0.5f;
    float d1 = (t1 - v1) * 0.5f;

    // output addressing
    int bc = row >> 7;                   // row / H2
    int i  = row & (H2 - 1);
    const int OW = 2 * W2;               // 256
    long long obase = ((long long)bc * (2 * H2) + 2 * i) * OW + (long long)col2 * 4;

    *reinterpret_cast<float4*>(out + obase)      = make_float4(a0, b0, a1, b1);
    *reinterpret_cast<float4*>(out + obase + OW) = make_float4(c0, d0, c1, d1);
}

extern "C" void kernel_launch(void* const* d_in, const int* in_sizes, int n_in,
                              void* d_out, int out_size)
{
    const float2* LL = (const float2*)d_in[0];
    const float2* LH = (const float2*)d_in[1];
    const float2* HL = (const float2*)d_in[2];
    const float2* HH = (const float2*)d_in[3];
    float* out = (float*)d_out;

    const int threads = 256;
    const int blocks = NTHREADS_TOTAL / threads;   // 32768
    idwt_haar_kernel<<<blocks, threads>>>(LL, LH, HL, HH, out);
}